// round 14
// baseline (speedup 1.0000x reference)
#include <cuda_runtime.h>
#include <cuda_fp16.h>
#include <cstdint>

#define N_NODES 100000
#define DIM     128
#define NREL    8
#define NEDGES  625000
#define NMAT    9
#define NCHUNKM 98                    // M-chunks of 1024 rows
#define MFRAG_PAD (NCHUNKM * 64)      // 6272 mfrags (16 rows each), padded
#define SCAN_C  ((N_NODES + 1023) / 1024)   // 98

// ---------------------------------------------------------------------------
// Device globals
// ---------------------------------------------------------------------------
// y layout TRANSPOSED: [node][rel][128] fp16 — per-src rows contiguous (2KB)
__device__ __half   g_yh[(size_t)N_NODES * NREL * DIM]; // 204.8 MB
__device__ int      g_deg[N_NODES * NREL];
__device__ int      g_sdeg[N_NODES];      // out-degree (edges with this src)
__device__ int      g_soff[N_NODES + 1];
__device__ int      g_cursor[N_NODES];
__device__ uint2    g_es[NEDGES];         // sorted by src: {src|rel<<17, dst}
__device__ float    g_esc[NEDGES];        // per-edge scale (1/deg), same order
__device__ int      g_is32;
// B fragments (fp16): chunk cg = mat*8+kfrag, 4KB: [nfrag16][lane32][reg2] u32
__device__ uint32_t g_wB[NMAT * 8 * 1024];              // 288 KB
// A fragments (fp16): [mfrag][kfrag8][lane32][reg4] u32, zero-padded
__device__ uint32_t g_xh[(size_t)MFRAG_PAD * 8 * 32 * 4];   // 25.7 MB

// ---------------------------------------------------------------------------
// helpers
// ---------------------------------------------------------------------------
__device__ __forceinline__ uint32_t smem_u32(const void* p) {
    uint32_t a;
    asm("{ .reg .u64 t; cvta.to.shared.u64 t, %1; cvt.u32.u64 %0, t; }"
        : "=r"(a) : "l"(p));
    return a;
}
__device__ __forceinline__ uint32_t pack_h2(__half a, __half b) {
    return (uint32_t)__half_as_ushort(a) | ((uint32_t)__half_as_ushort(b) << 16);
}
__device__ __forceinline__ uint32_t cvt2(float2 v) {
    return pack_h2(__float2half_rn(v.x), __float2half_rn(v.y));
}
__device__ __forceinline__ void mma_f16(float* c, uint32_t a0, uint32_t a1,
                                        uint32_t a2, uint32_t a3,
                                        uint32_t b0, uint32_t b1) {
    asm volatile(
        "mma.sync.aligned.m16n8k16.row.col.f32.f16.f16.f32 "
        "{%0,%1,%2,%3}, {%4,%5,%6,%7}, {%8,%9}, {%0,%1,%2,%3};"
        : "+f"(c[0]), "+f"(c[1]), "+f"(c[2]), "+f"(c[3])
        : "r"(a0), "r"(a1), "r"(a2), "r"(a3), "r"(b0), "r"(b1));
}
__device__ __forceinline__ void cp16(uint32_t smem_dst, const void* gsrc) {
    asm volatile("cp.async.cg.shared.global [%0], [%1], 16;"
                 :: "r"(smem_dst), "l"(gsrc));
}
__device__ __forceinline__ void cp_commit() {
    asm volatile("cp.async.commit_group;" ::: "memory");
}
template <int N>
__device__ __forceinline__ void cp_wait() {
    asm volatile("cp.async.wait_group %0;" :: "n"(N) : "memory");
}

// ---------------------------------------------------------------------------
// 0) zero deg/sdeg + (block 0) index dtype detection
// ---------------------------------------------------------------------------
__global__ void zero_detect_kernel(const void* __restrict__ ei) {
    int i = blockIdx.x * blockDim.x + threadIdx.x;
    if (i < N_NODES * NREL) g_deg[i] = 0;
    if (i < N_NODES) g_sdeg[i] = 0;
    if (blockIdx.x == 0 && threadIdx.x == 0) {
        const long long* p = (const long long*)ei;
        int is32 = 0;
        #pragma unroll 1
        for (int k = 0; k < 64; ++k) {
            long long v = p[k];
            if (v < 0 || v >= N_NODES) { is32 = 1; break; }
        }
        g_is32 = is32;
    }
}
__device__ __forceinline__ int load_idx(const void* p, long long i, int is32) {
    return is32 ? ((const int*)p)[i] : (int)((const long long*)p)[i];
}

// ---------------------------------------------------------------------------
// 1) weight prep: pack W (fp32 [mat][k][n]) into fp16 fragment chunks
// ---------------------------------------------------------------------------
__global__ void wprep_kernel(const float* __restrict__ wrel,
                             const float* __restrict__ wself) {
    int gid = blockIdx.x * blockDim.x + threadIdx.x;
    if (gid >= NMAT * 8 * 1024) return;
    int j  = gid & 1;
    int l  = (gid >> 1) & 31;
    int nf = (gid >> 6) & 15;
    int kk = (gid >> 10) & 7;
    int r  = gid >> 13;
    int t = l & 3, g = l >> 2;
    int n  = nf * 8 + g;
    int k0 = kk * 16 + t * 2 + (j ? 8 : 0);

    float w0, w1;
    if (r < 8) {
        w0 = wrel[((size_t)r * 128 + k0) * 128 + n];
        w1 = wrel[((size_t)r * 128 + k0 + 1) * 128 + n];
    } else {
        w0 = wself[(size_t)k0 * 128 + n];
        w1 = wself[(size_t)(k0 + 1) * 128 + n];
    }
    g_wB[gid] = cvt2(make_float2(w0, w1));
}

// ---------------------------------------------------------------------------
// 2) A-fragment prep: x (fp32) -> fp16 mma fragments, zero-padded
// ---------------------------------------------------------------------------
__global__ void xh_kernel(const float* __restrict__ x) {
    int gid = blockIdx.x * blockDim.x + threadIdx.x;
    if (gid >= MFRAG_PAD * 8 * 32) return;
    int lane = gid & 31;
    int kk   = (gid >> 5) & 7;
    int mf   = gid >> 8;
    int tq = lane & 3, gq = lane >> 2;
    int row0 = mf * 16 + gq;
    int row1 = row0 + 8;
    int c0 = kk * 16 + 2 * tq;
    int c2 = c0 + 8;
    float2 z = make_float2(0.f, 0.f);
    float2 p00 = (row0 < N_NODES) ? *(const float2*)(x + (size_t)row0 * DIM + c0) : z;
    float2 p10 = (row1 < N_NODES) ? *(const float2*)(x + (size_t)row1 * DIM + c0) : z;
    float2 p01 = (row0 < N_NODES) ? *(const float2*)(x + (size_t)row0 * DIM + c2) : z;
    float2 p11 = (row1 < N_NODES) ? *(const float2*)(x + (size_t)row1 * DIM + c2) : z;
    ((uint4*)g_xh)[gid] = make_uint4(cvt2(p00), cvt2(p10), cvt2(p01), cvt2(p11));
}

// ---------------------------------------------------------------------------
// 3) degree: per (dst,rel) for normalization, per src for the sort
// ---------------------------------------------------------------------------
__global__ void deg_kernel(const void* __restrict__ ei, const void* __restrict__ et) {
    int e = blockIdx.x * blockDim.x + threadIdx.x;
    if (e >= NEDGES) return;
    int is32 = g_is32;
    int src = load_idx(ei, e, is32);
    int dst = load_idx(ei, (long long)NEDGES + e, is32);
    int r   = load_idx(et, e, is32);
    atomicAdd(&g_deg[dst * NREL + r], 1);
    atomicAdd(&g_sdeg[src], 1);
}

// ---------------------------------------------------------------------------
// 4) exclusive scan over src degrees -> offsets + cursors (1 block)
// ---------------------------------------------------------------------------
__global__ __launch_bounds__(1024) void scan_kernel() {
    __shared__ int part[1024];
    int t = threadIdx.x;
    int base = t * SCAN_C;
    int loc[SCAN_C];
    int s = 0;
    #pragma unroll 1
    for (int i = 0; i < SCAN_C; ++i) {
        int idx = base + i;
        int v = (idx < N_NODES) ? g_sdeg[idx] : 0;
        loc[i] = s;
        s += v;
    }
    part[t] = s;
    __syncthreads();
    for (int d = 1; d < 1024; d <<= 1) {
        int v = part[t];
        int u = (t >= d) ? part[t - d] : 0;
        __syncthreads();
        part[t] = v + u;
        __syncthreads();
    }
    int excl = (t > 0) ? part[t - 1] : 0;
    #pragma unroll 1
    for (int i = 0; i < SCAN_C; ++i) {
        int idx = base + i;
        if (idx < N_NODES) {
            int o = excl + loc[i];
            g_soff[idx] = o;
            g_cursor[idx] = o;
        }
    }
    if (t == 1023) g_soff[N_NODES] = part[1023];
}

// ---------------------------------------------------------------------------
// 5) counting-sort edges by src; pre-fold scale
// ---------------------------------------------------------------------------
__global__ void sortsc_kernel(const void* __restrict__ ei,
                              const void* __restrict__ et) {
    int e = blockIdx.x * blockDim.x + threadIdx.x;
    if (e >= NEDGES) return;
    int is32 = g_is32;
    int src = load_idx(ei, e, is32);
    int dst = load_idx(ei, (long long)NEDGES + e, is32);
    int r   = load_idx(et, e, is32);
    int pos = atomicAdd(&g_cursor[src], 1);
    int d   = g_deg[dst * NREL + r];
    g_es[pos]  = make_uint2((uint32_t)src | ((uint32_t)r << 17), (uint32_t)dst);
    g_esc[pos] = 1.0f / (float)(d > 1 ? d : 1);
}

// ---------------------------------------------------------------------------
// 6) xw kernel, B-in-registers (R12 winner; y write goes to [node][rel][128])
// ---------------------------------------------------------------------------
__global__ __launch_bounds__(256, 2) void xw_kernel(
    const float* __restrict__ bias,
    float* __restrict__ out)
{
    __shared__ uint32_t sA[2][4][8][32][4];   // [buf][mfrag][kfrag][lane][reg] 32KB

    const int tid  = threadIdx.x;
    const int wid  = tid >> 5;
    const int lane = tid & 31;
    const int gq   = lane >> 2;
    const int tq   = lane & 3;
    const int wm   = wid & 1;
    const int wn   = wid >> 1;
    const int chunk = blockIdx.x;
    const int mat   = blockIdx.y;

    const uint32_t sA0 = smem_u32(&sA[0][0][0][0][0]);

    {
        const char* asrc = (const char*)(g_xh + (size_t)(chunk * 64) * 1024);
        #pragma unroll
        for (int rnd = 0; rnd < 4; ++rnd)
            cp16(sA0 + tid * 16 + rnd * 4096, asrc + tid * 16 + rnd * 4096);
        cp_commit();
    }

    uint2 B[8][4];
    {
        const uint32_t* bbase = g_wB + (size_t)mat * 8192 + lane * 2;
        #pragma unroll
        for (int kk = 0; kk < 8; ++kk)
            #pragma unroll
            for (int nf = 0; nf < 4; ++nf)
                B[kk][nf] = *(const uint2*)(bbase + kk * 1024 + (wn * 4 + nf) * 64);
    }

    float acc[32];
    const int rowb = chunk * 1024;

    #pragma unroll 1
    for (int st = 0; st < 16; ++st) {
        if (st + 1 < 16) {
            uint32_t sb = sA0 + ((st + 1) & 1) * 16384;
            const char* asrc = (const char*)(g_xh +
                (size_t)(chunk * 64 + (st + 1) * 4) * 1024);
            #pragma unroll
            for (int rnd = 0; rnd < 4; ++rnd)
                cp16(sb + tid * 16 + rnd * 4096, asrc + tid * 16 + rnd * 4096);
        }
        cp_commit();
        cp_wait<1>();
        __syncthreads();

        #pragma unroll
        for (int i = 0; i < 32; ++i) acc[i] = 0.f;

        const int buf = st & 1;
        #pragma unroll
        for (int kk = 0; kk < 8; ++kk) {
            uint4 a0 = *(const uint4*)&sA[buf][wm * 2 + 0][kk][lane][0];
            uint4 a1 = *(const uint4*)&sA[buf][wm * 2 + 1][kk][lane][0];
            #pragma unroll
            for (int nf = 0; nf < 4; ++nf) {
                mma_f16(&acc[nf * 4],      a0.x, a0.y, a0.z, a0.w,
                        B[kk][nf].x, B[kk][nf].y);
                mma_f16(&acc[16 + nf * 4], a1.x, a1.y, a1.z, a1.w,
                        B[kk][nf].x, B[kk][nf].y);
            }
        }

        #pragma unroll
        for (int i = 0; i < 2; ++i) {
            const int row0 = rowb + st * 64 + (wm * 2 + i) * 16 + gq;
            const int row1 = row0 + 8;
            const float* ac = &acc[i * 16];
            if (mat < 8) {
                if (row0 < N_NODES) {
                    __half* y0 = g_yh + ((size_t)row0 * NREL + mat) * DIM;
                    #pragma unroll
                    for (int nf = 0; nf < 4; ++nf) {
                        uint32_t p = pack_h2(__float2half_rn(ac[nf*4+0]),
                                             __float2half_rn(ac[nf*4+1]));
                        __stcs((float*)(y0 + (wn*4+nf)*8 + 2*tq), __uint_as_float(p));
                    }
                }
                if (row1 < N_NODES) {
                    __half* y1 = g_yh + ((size_t)row1 * NREL + mat) * DIM;
                    #pragma unroll
                    for (int nf = 0; nf < 4; ++nf) {
                        uint32_t p = pack_h2(__float2half_rn(ac[nf*4+2]),
                                             __float2half_rn(ac[nf*4+3]));
                        __stcs((float*)(y1 + (wn*4+nf)*8 + 2*tq), __uint_as_float(p));
                    }
                }
            } else {
                #pragma unroll
                for (int nf = 0; nf < 4; ++nf) {
                    const int col = (wn * 4 + nf) * 8 + 2 * tq;
                    float2 bv = *(const float2*)(bias + col);
                    if (row0 < N_NODES)
                        *(float2*)(out + (size_t)row0 * DIM + col) =
                            make_float2(ac[nf*4+0] + bv.x, ac[nf*4+1] + bv.y);
                    if (row1 < N_NODES)
                        *(float2*)(out + (size_t)row1 * DIM + col) =
                            make_float2(ac[nf*4+2] + bv.x, ac[nf*4+3] + bv.y);
                }
            }
        }
        __syncthreads();
    }
}

// ---------------------------------------------------------------------------
// 7) scatter over src-sorted edges: 16 lanes/edge.
//    y reads sweep [node][rel] near-sequentially; atomics into L2-hot out.
// ---------------------------------------------------------------------------
__global__ void scatter_kernel(float* __restrict__ out) {
    int gtid = blockIdx.x * blockDim.x + threadIdx.x;
    int e    = gtid >> 4;
    int l    = gtid & 15;
    if (e >= NEDGES) return;

    uint2 rec = g_es[e];                   // broadcast across 16 lanes
    float s   = g_esc[e];
    int src = rec.x & 0x1FFFF;
    int r   = (rec.x >> 17) & 7;
    int dst = (int)rec.y;

    const __half* yrow = g_yh + ((size_t)src * NREL + r) * DIM;
    uint32_t u0, u1, u2, u3;
    asm volatile("ld.global.cs.v4.u32 {%0,%1,%2,%3}, [%4];"
                 : "=r"(u0), "=r"(u1), "=r"(u2), "=r"(u3)
                 : "l"(yrow + l * 8));
    float2 f0 = __half22float2(*reinterpret_cast<__half2*>(&u0));
    float2 f1 = __half22float2(*reinterpret_cast<__half2*>(&u1));
    float2 f2 = __half22float2(*reinterpret_cast<__half2*>(&u2));
    float2 f3 = __half22float2(*reinterpret_cast<__half2*>(&u3));

    float* o = out + (size_t)dst * DIM + l * 8;
    asm volatile("red.global.add.v4.f32 [%0], {%1,%2,%3,%4};"
                 :: "l"(o), "f"(f0.x * s), "f"(f0.y * s),
                    "f"(f1.x * s), "f"(f1.y * s) : "memory");
    asm volatile("red.global.add.v4.f32 [%0], {%1,%2,%3,%4};"
                 :: "l"(o + 4), "f"(f2.x * s), "f"(f2.y * s),
                    "f"(f3.x * s), "f"(f3.y * s) : "memory");
}

// ---------------------------------------------------------------------------
// launch
// ---------------------------------------------------------------------------
extern "C" void kernel_launch(void* const* d_in, const int* in_sizes, int n_in,
                              void* d_out, int out_size) {
    const float* x     = (const float*)d_in[0];
    const void*  ei    = d_in[1];
    const void*  et    = d_in[2];
    const float* wrel  = (const float*)d_in[3];
    const float* wself = (const float*)d_in[4];
    const float* bias  = (const float*)d_in[5];
    float*       out   = (float*)d_out;

    zero_detect_kernel<<<(N_NODES * NREL + 255) / 256, 256>>>(ei);
    wprep_kernel<<<(NMAT * 8 * 1024 + 255) / 256, 256>>>(wrel, wself);
    xh_kernel<<<(MFRAG_PAD * 8 * 32 + 255) / 256, 256>>>(x);
    deg_kernel<<<(NEDGES + 255) / 256, 256>>>(ei, et);
    scan_kernel<<<1, 1024>>>();
    sortsc_kernel<<<(NEDGES + 255) / 256, 256>>>(ei, et);
    xw_kernel<<<dim3(NCHUNKM, NMAT), 256>>>(bias, out);
    scatter_kernel<<<((size_t)NEDGES * 16 + 255) / 256, 256>>>(out);
}

// round 15
// speedup vs baseline: 1.6251x; 1.6251x over previous
#include <cuda_runtime.h>
#include <cuda_fp16.h>
#include <cstdint>

#define N_NODES 100000
#define DIM     128
#define NREL    8
#define NEDGES  625000
#define NMAT    9
#define NCHUNKM 98                    // M-chunks of 1024 rows
#define MFRAG_PAD (NCHUNKM * 64)      // 6272 mfrags (16 rows each), padded

// ---------------------------------------------------------------------------
// Device globals
// ---------------------------------------------------------------------------
__device__ __half   g_yh[(size_t)NREL * N_NODES * DIM]; // 204.8 MB fp16
__device__ int      g_deg[N_NODES * NREL];
__device__ int      g_is32;
__device__ uint2    g_epk[NEDGES];       // {src|rel<<17, dst} in edge order
__device__ float    g_esc[NEDGES];       // 1/max(deg[dst,rel],1) in edge order
// B fragments (fp16): chunk cg = mat*8+kfrag, 4KB: [nfrag16][lane32][reg2] u32
__device__ uint32_t g_wB[NMAT * 8 * 1024];              // 288 KB
// A fragments (fp16): [mfrag][kfrag8][lane32][reg4] u32, zero-padded
__device__ uint32_t g_xh[(size_t)MFRAG_PAD * 8 * 32 * 4];   // 25.7 MB

// ---------------------------------------------------------------------------
// helpers
// ---------------------------------------------------------------------------
__device__ __forceinline__ uint32_t smem_u32(const void* p) {
    uint32_t a;
    asm("{ .reg .u64 t; cvta.to.shared.u64 t, %1; cvt.u32.u64 %0, t; }"
        : "=r"(a) : "l"(p));
    return a;
}
__device__ __forceinline__ uint32_t pack_h2(__half a, __half b) {
    return (uint32_t)__half_as_ushort(a) | ((uint32_t)__half_as_ushort(b) << 16);
}
__device__ __forceinline__ uint32_t cvt2(float2 v) {
    return pack_h2(__float2half_rn(v.x), __float2half_rn(v.y));
}
__device__ __forceinline__ void mma_f16(float* c, uint32_t a0, uint32_t a1,
                                        uint32_t a2, uint32_t a3,
                                        uint32_t b0, uint32_t b1) {
    asm volatile(
        "mma.sync.aligned.m16n8k16.row.col.f32.f16.f16.f32 "
        "{%0,%1,%2,%3}, {%4,%5,%6,%7}, {%8,%9}, {%0,%1,%2,%3};"
        : "+f"(c[0]), "+f"(c[1]), "+f"(c[2]), "+f"(c[3])
        : "r"(a0), "r"(a1), "r"(a2), "r"(a3), "r"(b0), "r"(b1));
}
__device__ __forceinline__ void cp16(uint32_t smem_dst, const void* gsrc) {
    asm volatile("cp.async.cg.shared.global [%0], [%1], 16;"
                 :: "r"(smem_dst), "l"(gsrc));
}
__device__ __forceinline__ void cp_commit() {
    asm volatile("cp.async.commit_group;" ::: "memory");
}
template <int N>
__device__ __forceinline__ void cp_wait() {
    asm volatile("cp.async.wait_group %0;" :: "n"(N) : "memory");
}

// ---------------------------------------------------------------------------
// 0) zero deg + (block 0) index dtype detection
// ---------------------------------------------------------------------------
__global__ void zero_detect_kernel(const void* __restrict__ ei) {
    int i = blockIdx.x * blockDim.x + threadIdx.x;
    if (i < N_NODES * NREL) g_deg[i] = 0;
    if (blockIdx.x == 0 && threadIdx.x == 0) {
        const long long* p = (const long long*)ei;
        int is32 = 0;
        #pragma unroll 1
        for (int k = 0; k < 64; ++k) {
            long long v = p[k];
            if (v < 0 || v >= N_NODES) { is32 = 1; break; }
        }
        g_is32 = is32;
    }
}
__device__ __forceinline__ int load_idx(const void* p, long long i, int is32) {
    return is32 ? ((const int*)p)[i] : (int)((const long long*)p)[i];
}

// ---------------------------------------------------------------------------
// 1) weight prep: pack W (fp32 [mat][k][n]) into fp16 fragment chunks
// ---------------------------------------------------------------------------
__global__ void wprep_kernel(const float* __restrict__ wrel,
                             const float* __restrict__ wself) {
    int gid = blockIdx.x * blockDim.x + threadIdx.x;
    if (gid >= NMAT * 8 * 1024) return;
    int j  = gid & 1;
    int l  = (gid >> 1) & 31;
    int nf = (gid >> 6) & 15;
    int kk = (gid >> 10) & 7;
    int r  = gid >> 13;
    int t = l & 3, g = l >> 2;
    int n  = nf * 8 + g;
    int k0 = kk * 16 + t * 2 + (j ? 8 : 0);

    float w0, w1;
    if (r < 8) {
        w0 = wrel[((size_t)r * 128 + k0) * 128 + n];
        w1 = wrel[((size_t)r * 128 + k0 + 1) * 128 + n];
    } else {
        w0 = wself[(size_t)k0 * 128 + n];
        w1 = wself[(size_t)(k0 + 1) * 128 + n];
    }
    g_wB[gid] = cvt2(make_float2(w0, w1));
}

// ---------------------------------------------------------------------------
// 2) A-fragment prep: x (fp32) -> fp16 mma fragments, zero-padded
// ---------------------------------------------------------------------------
__global__ void xh_kernel(const float* __restrict__ x) {
    int gid = blockIdx.x * blockDim.x + threadIdx.x;
    if (gid >= MFRAG_PAD * 8 * 32) return;
    int lane = gid & 31;
    int kk   = (gid >> 5) & 7;
    int mf   = gid >> 8;
    int tq = lane & 3, gq = lane >> 2;
    int row0 = mf * 16 + gq;
    int row1 = row0 + 8;
    int c0 = kk * 16 + 2 * tq;
    int c2 = c0 + 8;
    float2 z = make_float2(0.f, 0.f);
    float2 p00 = (row0 < N_NODES) ? *(const float2*)(x + (size_t)row0 * DIM + c0) : z;
    float2 p10 = (row1 < N_NODES) ? *(const float2*)(x + (size_t)row1 * DIM + c0) : z;
    float2 p01 = (row0 < N_NODES) ? *(const float2*)(x + (size_t)row0 * DIM + c2) : z;
    float2 p11 = (row1 < N_NODES) ? *(const float2*)(x + (size_t)row1 * DIM + c2) : z;
    ((uint4*)g_xh)[gid] = make_uint4(cvt2(p00), cvt2(p10), cvt2(p01), cvt2(p11));
}

// ---------------------------------------------------------------------------
// 3) degree
// ---------------------------------------------------------------------------
__global__ void deg_kernel(const void* __restrict__ ei, const void* __restrict__ et) {
    int e = blockIdx.x * blockDim.x + threadIdx.x;
    if (e >= NEDGES) return;
    int is32 = g_is32;
    int dst = load_idx(ei, (long long)NEDGES + e, is32);
    int r   = load_idx(et, e, is32);
    atomicAdd(&g_deg[dst * NREL + r], 1);
}

// ---------------------------------------------------------------------------
// 4) edge pack: {src|rel<<17, dst} + prefolded scale, edge order
// ---------------------------------------------------------------------------
__global__ void epack_kernel(const void* __restrict__ ei,
                             const void* __restrict__ et) {
    int e = blockIdx.x * blockDim.x + threadIdx.x;
    if (e >= NEDGES) return;
    int is32 = g_is32;
    int src = load_idx(ei, e, is32);
    int dst = load_idx(ei, (long long)NEDGES + e, is32);
    int r   = load_idx(et, e, is32);
    int d   = g_deg[dst * NREL + r];
    g_epk[e] = make_uint2((uint32_t)src | ((uint32_t)r << 17), (uint32_t)dst);
    g_esc[e] = 1.0f / (float)(d > 1 ? d : 1);
}

// ---------------------------------------------------------------------------
// 5) xw kernel, B-in-registers (R12 winner, y layout [rel][node][128])
// ---------------------------------------------------------------------------
__global__ __launch_bounds__(256, 2) void xw_kernel(
    const float* __restrict__ bias,
    float* __restrict__ out)
{
    __shared__ uint32_t sA[2][4][8][32][4];   // [buf][mfrag][kfrag][lane][reg] 32KB

    const int tid  = threadIdx.x;
    const int wid  = tid >> 5;
    const int lane = tid & 31;
    const int gq   = lane >> 2;
    const int tq   = lane & 3;
    const int wm   = wid & 1;            // m half (2 mfrags)
    const int wn   = wid >> 1;           // n quarter (4 nfrags)
    const int chunk = blockIdx.x;
    const int mat   = blockIdx.y;

    const uint32_t sA0 = smem_u32(&sA[0][0][0][0][0]);

    // ---- prologue: cp.async A subtile 0 (16KB)
    {
        const char* asrc = (const char*)(g_xh + (size_t)(chunk * 64) * 1024);
        #pragma unroll
        for (int rnd = 0; rnd < 4; ++rnd)
            cp16(sA0 + tid * 16 + rnd * 4096, asrc + tid * 16 + rnd * 4096);
        cp_commit();
    }

    // ---- load B fragments into registers (L2-hot, coalesced 8B/lane)
    uint2 B[8][4];
    {
        const uint32_t* bbase = g_wB + (size_t)mat * 8192 + lane * 2;
        #pragma unroll
        for (int kk = 0; kk < 8; ++kk)
            #pragma unroll
            for (int nf = 0; nf < 4; ++nf)
                B[kk][nf] = *(const uint2*)(bbase + kk * 1024 + (wn * 4 + nf) * 64);
    }

    float acc[32];                        // [i 2][nf 4][4]
    const int rowb = chunk * 1024;

    #pragma unroll 1
    for (int st = 0; st < 16; ++st) {
        if (st + 1 < 16) {
            uint32_t sb = sA0 + ((st + 1) & 1) * 16384;
            const char* asrc = (const char*)(g_xh +
                (size_t)(chunk * 64 + (st + 1) * 4) * 1024);
            #pragma unroll
            for (int rnd = 0; rnd < 4; ++rnd)
                cp16(sb + tid * 16 + rnd * 4096, asrc + tid * 16 + rnd * 4096);
        }
        cp_commit();
        cp_wait<1>();
        __syncthreads();

        #pragma unroll
        for (int i = 0; i < 32; ++i) acc[i] = 0.f;

        const int buf = st & 1;
        #pragma unroll
        for (int kk = 0; kk < 8; ++kk) {
            uint4 a0 = *(const uint4*)&sA[buf][wm * 2 + 0][kk][lane][0];
            uint4 a1 = *(const uint4*)&sA[buf][wm * 2 + 1][kk][lane][0];
            #pragma unroll
            for (int nf = 0; nf < 4; ++nf) {
                mma_f16(&acc[nf * 4],      a0.x, a0.y, a0.z, a0.w,
                        B[kk][nf].x, B[kk][nf].y);
                mma_f16(&acc[16 + nf * 4], a1.x, a1.y, a1.z, a1.w,
                        B[kk][nf].x, B[kk][nf].y);
            }
        }

        // ---- epilogue for this subtile (2 mfrags per warp)
        #pragma unroll
        for (int i = 0; i < 2; ++i) {
            const int row0 = rowb + st * 64 + (wm * 2 + i) * 16 + gq;
            const int row1 = row0 + 8;
            const float* ac = &acc[i * 16];
            if (mat < 8) {
                if (row0 < N_NODES) {
                    __half* y0 = g_yh + ((size_t)mat * N_NODES + row0) * DIM;
                    #pragma unroll
                    for (int nf = 0; nf < 4; ++nf) {
                        uint32_t p = pack_h2(__float2half_rn(ac[nf*4+0]),
                                             __float2half_rn(ac[nf*4+1]));
                        __stcs((float*)(y0 + (wn*4+nf)*8 + 2*tq), __uint_as_float(p));
                    }
                }
                if (row1 < N_NODES) {
                    __half* y1 = g_yh + ((size_t)mat * N_NODES + row1) * DIM;
                    #pragma unroll
                    for (int nf = 0; nf < 4; ++nf) {
                        uint32_t p = pack_h2(__float2half_rn(ac[nf*4+2]),
                                             __float2half_rn(ac[nf*4+3]));
                        __stcs((float*)(y1 + (wn*4+nf)*8 + 2*tq), __uint_as_float(p));
                    }
                }
            } else {
                #pragma unroll
                for (int nf = 0; nf < 4; ++nf) {
                    const int col = (wn * 4 + nf) * 8 + 2 * tq;
                    float2 bv = *(const float2*)(bias + col);
                    if (row0 < N_NODES)
                        *(float2*)(out + (size_t)row0 * DIM + col) =
                            make_float2(ac[nf*4+0] + bv.x, ac[nf*4+1] + bv.y);
                    if (row1 < N_NODES)
                        *(float2*)(out + (size_t)row1 * DIM + col) =
                            make_float2(ac[nf*4+2] + bv.x, ac[nf*4+3] + bv.y);
                }
            }
        }
        __syncthreads();
    }
}

// ---------------------------------------------------------------------------
// 6) scatter: 16 lanes/edge over packed records:
//    out[dst] += y[rel][src] * scale
// ---------------------------------------------------------------------------
__global__ void scatter_kernel(float* __restrict__ out) {
    int gtid = blockIdx.x * blockDim.x + threadIdx.x;
    int e    = gtid >> 4;
    int l    = gtid & 15;
    if (e >= NEDGES) return;

    uint2 rec = __ldg(&g_epk[e]);          // broadcast across 16 lanes
    float s   = __ldg(&g_esc[e]);
    int src = rec.x & 0x1FFFF;
    int r   = (rec.x >> 17) & 7;
    int dst = (int)rec.y;

    const __half* yrow = g_yh + ((size_t)r * N_NODES + src) * DIM;
    uint32_t u0, u1, u2, u3;
    asm volatile("ld.global.cs.v4.u32 {%0,%1,%2,%3}, [%4];"
                 : "=r"(u0), "=r"(u1), "=r"(u2), "=r"(u3)
                 : "l"(yrow + l * 8));
    float2 f0 = __half22float2(*reinterpret_cast<__half2*>(&u0));
    float2 f1 = __half22float2(*reinterpret_cast<__half2*>(&u1));
    float2 f2 = __half22float2(*reinterpret_cast<__half2*>(&u2));
    float2 f3 = __half22float2(*reinterpret_cast<__half2*>(&u3));

    float* o = out + (size_t)dst * DIM + l * 8;
    asm volatile("red.global.add.v4.f32 [%0], {%1,%2,%3,%4};"
                 :: "l"(o), "f"(f0.x * s), "f"(f0.y * s),
                    "f"(f1.x * s), "f"(f1.y * s) : "memory");
    asm volatile("red.global.add.v4.f32 [%0], {%1,%2,%3,%4};"
                 :: "l"(o + 4), "f"(f2.x * s), "f"(f2.y * s),
                    "f"(f3.x * s), "f"(f3.y * s) : "memory");
}

// ---------------------------------------------------------------------------
// launch
// ---------------------------------------------------------------------------
extern "C" void kernel_launch(void* const* d_in, const int* in_sizes, int n_in,
                              void* d_out, int out_size) {
    const float* x     = (const float*)d_in[0];
    const void*  ei    = d_in[1];
    const void*  et    = d_in[2];
    const float* wrel  = (const float*)d_in[3];
    const float* wself = (const float*)d_in[4];
    const float* bias  = (const float*)d_in[5];
    float*       out   = (float*)d_out;

    zero_detect_kernel<<<(N_NODES * NREL + 255) / 256, 256>>>(ei);
    wprep_kernel<<<(NMAT * 8 * 1024 + 255) / 256, 256>>>(wrel, wself);
    xh_kernel<<<(MFRAG_PAD * 8 * 32 + 255) / 256, 256>>>(x);
    deg_kernel<<<(NEDGES + 255) / 256, 256>>>(ei, et);
    epack_kernel<<<(NEDGES + 255) / 256, 256>>>(ei, et);
    xw_kernel<<<dim3(NCHUNKM, NMAT), 256>>>(bias, out);
    scatter_kernel<<<((size_t)NEDGES * 16 + 255) / 256, 256>>>(out);
}

// round 16
// speedup vs baseline: 1.6359x; 1.0067x over previous
#include <cuda_runtime.h>
#include <cuda_fp16.h>
#include <cstdint>

#define N_NODES 100000
#define DIM     128
#define NREL    8
#define NEDGES  625000
#define NMAT    9
#define NCHUNKM 98                    // M-chunks of 1024 rows
#define MFRAG_PAD (NCHUNKM * 64)      // 6272 mfrags (16 rows each), padded

// ---------------------------------------------------------------------------
// Device globals
// ---------------------------------------------------------------------------
__device__ __half   g_yh[(size_t)NREL * N_NODES * DIM]; // 204.8 MB fp16
__device__ int      g_deg[N_NODES * NREL];
__device__ int      g_is32;
__device__ uint2    g_epk[NEDGES];       // {src|rel<<17, dst} in edge order
__device__ float    g_esc[NEDGES];       // 1/max(deg[dst,rel],1) in edge order
// B fragments (fp16): chunk cg = mat*8+kfrag, 4KB: [nfrag16][lane32][reg2] u32
__device__ uint32_t g_wB[NMAT * 8 * 1024];              // 288 KB
// A fragments (fp16): [mfrag][kfrag8][lane32][reg4] u32, zero-padded
__device__ uint32_t g_xh[(size_t)MFRAG_PAD * 8 * 32 * 4];   // 25.7 MB

// ---------------------------------------------------------------------------
// helpers
// ---------------------------------------------------------------------------
__device__ __forceinline__ uint32_t smem_u32(const void* p) {
    uint32_t a;
    asm("{ .reg .u64 t; cvta.to.shared.u64 t, %1; cvt.u32.u64 %0, t; }"
        : "=r"(a) : "l"(p));
    return a;
}
__device__ __forceinline__ uint32_t pack_h2(__half a, __half b) {
    return (uint32_t)__half_as_ushort(a) | ((uint32_t)__half_as_ushort(b) << 16);
}
__device__ __forceinline__ uint32_t cvt2(float2 v) {
    return pack_h2(__float2half_rn(v.x), __float2half_rn(v.y));
}
__device__ __forceinline__ void mma_f16(float* c, uint32_t a0, uint32_t a1,
                                        uint32_t a2, uint32_t a3,
                                        uint32_t b0, uint32_t b1) {
    asm volatile(
        "mma.sync.aligned.m16n8k16.row.col.f32.f16.f16.f32 "
        "{%0,%1,%2,%3}, {%4,%5,%6,%7}, {%8,%9}, {%0,%1,%2,%3};"
        : "+f"(c[0]), "+f"(c[1]), "+f"(c[2]), "+f"(c[3])
        : "r"(a0), "r"(a1), "r"(a2), "r"(a3), "r"(b0), "r"(b1));
}
__device__ __forceinline__ void cp16(uint32_t smem_dst, const void* gsrc) {
    asm volatile("cp.async.cg.shared.global [%0], [%1], 16;"
                 :: "r"(smem_dst), "l"(gsrc));
}
__device__ __forceinline__ void cp_commit() {
    asm volatile("cp.async.commit_group;" ::: "memory");
}
template <int N>
__device__ __forceinline__ void cp_wait() {
    asm volatile("cp.async.wait_group %0;" :: "n"(N) : "memory");
}

// ---------------------------------------------------------------------------
// 0) zero deg + (block 0) index dtype detection
// ---------------------------------------------------------------------------
__global__ void zero_detect_kernel(const void* __restrict__ ei) {
    int i = blockIdx.x * blockDim.x + threadIdx.x;
    if (i < N_NODES * NREL) g_deg[i] = 0;
    if (blockIdx.x == 0 && threadIdx.x == 0) {
        const long long* p = (const long long*)ei;
        int is32 = 0;
        #pragma unroll 1
        for (int k = 0; k < 64; ++k) {
            long long v = p[k];
            if (v < 0 || v >= N_NODES) { is32 = 1; break; }
        }
        g_is32 = is32;
    }
}
__device__ __forceinline__ int load_idx(const void* p, long long i, int is32) {
    return is32 ? ((const int*)p)[i] : (int)((const long long*)p)[i];
}

// ---------------------------------------------------------------------------
// 1) weight prep: pack W (fp32 [mat][k][n]) into fp16 fragment chunks
// ---------------------------------------------------------------------------
__global__ void wprep_kernel(const float* __restrict__ wrel,
                             const float* __restrict__ wself) {
    int gid = blockIdx.x * blockDim.x + threadIdx.x;
    if (gid >= NMAT * 8 * 1024) return;
    int j  = gid & 1;
    int l  = (gid >> 1) & 31;
    int nf = (gid >> 6) & 15;
    int kk = (gid >> 10) & 7;
    int r  = gid >> 13;
    int t = l & 3, g = l >> 2;
    int n  = nf * 8 + g;
    int k0 = kk * 16 + t * 2 + (j ? 8 : 0);

    float w0, w1;
    if (r < 8) {
        w0 = wrel[((size_t)r * 128 + k0) * 128 + n];
        w1 = wrel[((size_t)r * 128 + k0 + 1) * 128 + n];
    } else {
        w0 = wself[(size_t)k0 * 128 + n];
        w1 = wself[(size_t)(k0 + 1) * 128 + n];
    }
    g_wB[gid] = cvt2(make_float2(w0, w1));
}

// ---------------------------------------------------------------------------
// 2) A-fragment prep: x (fp32) -> fp16 mma fragments, zero-padded
// ---------------------------------------------------------------------------
__global__ void xh_kernel(const float* __restrict__ x) {
    int gid = blockIdx.x * blockDim.x + threadIdx.x;
    if (gid >= MFRAG_PAD * 8 * 32) return;
    int lane = gid & 31;
    int kk   = (gid >> 5) & 7;
    int mf   = gid >> 8;
    int tq = lane & 3, gq = lane >> 2;
    int row0 = mf * 16 + gq;
    int row1 = row0 + 8;
    int c0 = kk * 16 + 2 * tq;
    int c2 = c0 + 8;
    float2 z = make_float2(0.f, 0.f);
    float2 p00 = (row0 < N_NODES) ? *(const float2*)(x + (size_t)row0 * DIM + c0) : z;
    float2 p10 = (row1 < N_NODES) ? *(const float2*)(x + (size_t)row1 * DIM + c0) : z;
    float2 p01 = (row0 < N_NODES) ? *(const float2*)(x + (size_t)row0 * DIM + c2) : z;
    float2 p11 = (row1 < N_NODES) ? *(const float2*)(x + (size_t)row1 * DIM + c2) : z;
    ((uint4*)g_xh)[gid] = make_uint4(cvt2(p00), cvt2(p10), cvt2(p01), cvt2(p11));
}

// ---------------------------------------------------------------------------
// 3) degree
// ---------------------------------------------------------------------------
__global__ void deg_kernel(const void* __restrict__ ei, const void* __restrict__ et) {
    int e = blockIdx.x * blockDim.x + threadIdx.x;
    if (e >= NEDGES) return;
    int is32 = g_is32;
    int dst = load_idx(ei, (long long)NEDGES + e, is32);
    int r   = load_idx(et, e, is32);
    atomicAdd(&g_deg[dst * NREL + r], 1);
}

// ---------------------------------------------------------------------------
// 4) edge pack: {src|rel<<17, dst} + prefolded scale, edge order
// ---------------------------------------------------------------------------
__global__ void epack_kernel(const void* __restrict__ ei,
                             const void* __restrict__ et) {
    int e = blockIdx.x * blockDim.x + threadIdx.x;
    if (e >= NEDGES) return;
    int is32 = g_is32;
    int src = load_idx(ei, e, is32);
    int dst = load_idx(ei, (long long)NEDGES + e, is32);
    int r   = load_idx(et, e, is32);
    int d   = g_deg[dst * NREL + r];
    g_epk[e] = make_uint2((uint32_t)src | ((uint32_t)r << 17), (uint32_t)dst);
    g_esc[e] = 1.0f / (float)(d > 1 ? d : 1);
}

// ---------------------------------------------------------------------------
// 5) xw kernel, B-in-registers (R12 winner, y layout [rel][node][128])
// ---------------------------------------------------------------------------
__global__ __launch_bounds__(256, 2) void xw_kernel(
    const float* __restrict__ bias,
    float* __restrict__ out)
{
    __shared__ uint32_t sA[2][4][8][32][4];   // [buf][mfrag][kfrag][lane][reg] 32KB

    const int tid  = threadIdx.x;
    const int wid  = tid >> 5;
    const int lane = tid & 31;
    const int gq   = lane >> 2;
    const int tq   = lane & 3;
    const int wm   = wid & 1;            // m half (2 mfrags)
    const int wn   = wid >> 1;           // n quarter (4 nfrags)
    const int chunk = blockIdx.x;
    const int mat   = blockIdx.y;

    const uint32_t sA0 = smem_u32(&sA[0][0][0][0][0]);

    // ---- prologue: cp.async A subtile 0 (16KB)
    {
        const char* asrc = (const char*)(g_xh + (size_t)(chunk * 64) * 1024);
        #pragma unroll
        for (int rnd = 0; rnd < 4; ++rnd)
            cp16(sA0 + tid * 16 + rnd * 4096, asrc + tid * 16 + rnd * 4096);
        cp_commit();
    }

    // ---- load B fragments into registers (L2-hot, coalesced 8B/lane)
    uint2 B[8][4];
    {
        const uint32_t* bbase = g_wB + (size_t)mat * 8192 + lane * 2;
        #pragma unroll
        for (int kk = 0; kk < 8; ++kk)
            #pragma unroll
            for (int nf = 0; nf < 4; ++nf)
                B[kk][nf] = *(const uint2*)(bbase + kk * 1024 + (wn * 4 + nf) * 64);
    }

    float acc[32];                        // [i 2][nf 4][4]
    const int rowb = chunk * 1024;

    #pragma unroll 1
    for (int st = 0; st < 16; ++st) {
        if (st + 1 < 16) {
            uint32_t sb = sA0 + ((st + 1) & 1) * 16384;
            const char* asrc = (const char*)(g_xh +
                (size_t)(chunk * 64 + (st + 1) * 4) * 1024);
            #pragma unroll
            for (int rnd = 0; rnd < 4; ++rnd)
                cp16(sb + tid * 16 + rnd * 4096, asrc + tid * 16 + rnd * 4096);
        }
        cp_commit();
        cp_wait<1>();
        __syncthreads();

        #pragma unroll
        for (int i = 0; i < 32; ++i) acc[i] = 0.f;

        const int buf = st & 1;
        #pragma unroll
        for (int kk = 0; kk < 8; ++kk) {
            uint4 a0 = *(const uint4*)&sA[buf][wm * 2 + 0][kk][lane][0];
            uint4 a1 = *(const uint4*)&sA[buf][wm * 2 + 1][kk][lane][0];
            #pragma unroll
            for (int nf = 0; nf < 4; ++nf) {
                mma_f16(&acc[nf * 4],      a0.x, a0.y, a0.z, a0.w,
                        B[kk][nf].x, B[kk][nf].y);
                mma_f16(&acc[16 + nf * 4], a1.x, a1.y, a1.z, a1.w,
                        B[kk][nf].x, B[kk][nf].y);
            }
        }

        // ---- epilogue for this subtile (2 mfrags per warp)
        #pragma unroll
        for (int i = 0; i < 2; ++i) {
            const int row0 = rowb + st * 64 + (wm * 2 + i) * 16 + gq;
            const int row1 = row0 + 8;
            const float* ac = &acc[i * 16];
            if (mat < 8) {
                if (row0 < N_NODES) {
                    __half* y0 = g_yh + ((size_t)mat * N_NODES + row0) * DIM;
                    #pragma unroll
                    for (int nf = 0; nf < 4; ++nf) {
                        uint32_t p = pack_h2(__float2half_rn(ac[nf*4+0]),
                                             __float2half_rn(ac[nf*4+1]));
                        __stcs((float*)(y0 + (wn*4+nf)*8 + 2*tq), __uint_as_float(p));
                    }
                }
                if (row1 < N_NODES) {
                    __half* y1 = g_yh + ((size_t)mat * N_NODES + row1) * DIM;
                    #pragma unroll
                    for (int nf = 0; nf < 4; ++nf) {
                        uint32_t p = pack_h2(__float2half_rn(ac[nf*4+2]),
                                             __float2half_rn(ac[nf*4+3]));
                        __stcs((float*)(y1 + (wn*4+nf)*8 + 2*tq), __uint_as_float(p));
                    }
                }
            } else {
                #pragma unroll
                for (int nf = 0; nf < 4; ++nf) {
                    const int col = (wn * 4 + nf) * 8 + 2 * tq;
                    float2 bv = *(const float2*)(bias + col);
                    if (row0 < N_NODES)
                        *(float2*)(out + (size_t)row0 * DIM + col) =
                            make_float2(ac[nf*4+0] + bv.x, ac[nf*4+1] + bv.y);
                    if (row1 < N_NODES)
                        *(float2*)(out + (size_t)row1 * DIM + col) =
                            make_float2(ac[nf*4+2] + bv.x, ac[nf*4+3] + bv.y);
                }
            }
        }
        __syncthreads();
    }
}

// ---------------------------------------------------------------------------
// 6) scatter: 16 lanes/edge over packed records:
//    out[dst] += y[rel][src] * scale
// ---------------------------------------------------------------------------
__global__ void scatter_kernel(float* __restrict__ out) {
    int gtid = blockIdx.x * blockDim.x + threadIdx.x;
    int e    = gtid >> 4;
    int l    = gtid & 15;
    if (e >= NEDGES) return;

    uint2 rec = __ldg(&g_epk[e]);          // broadcast across 16 lanes
    float s   = __ldg(&g_esc[e]);
    int src = rec.x & 0x1FFFF;
    int r   = (rec.x >> 17) & 7;
    int dst = (int)rec.y;

    const __half* yrow = g_yh + ((size_t)r * N_NODES + src) * DIM;
    uint32_t u0, u1, u2, u3;
    asm volatile("ld.global.cs.v4.u32 {%0,%1,%2,%3}, [%4];"
                 : "=r"(u0), "=r"(u1), "=r"(u2), "=r"(u3)
                 : "l"(yrow + l * 8));
    float2 f0 = __half22float2(*reinterpret_cast<__half2*>(&u0));
    float2 f1 = __half22float2(*reinterpret_cast<__half2*>(&u1));
    float2 f2 = __half22float2(*reinterpret_cast<__half2*>(&u2));
    float2 f3 = __half22float2(*reinterpret_cast<__half2*>(&u3));

    float* o = out + (size_t)dst * DIM + l * 8;
    asm volatile("red.global.add.v4.f32 [%0], {%1,%2,%3,%4};"
                 :: "l"(o), "f"(f0.x * s), "f"(f0.y * s),
                    "f"(f1.x * s), "f"(f1.y * s) : "memory");
    asm volatile("red.global.add.v4.f32 [%0], {%1,%2,%3,%4};"
                 :: "l"(o + 4), "f"(f2.x * s), "f"(f2.y * s),
                    "f"(f3.x * s), "f"(f3.y * s) : "memory");
}

// ---------------------------------------------------------------------------
// launch: minimal two-stream fork.
//   s1:      zero_detect -> deg -> epack            (edge prep, ~22us)
//   stream0: wprep -> xh -> xw                      (GEMM chain, ~97us)
//   join: stream0 waits s1, then scatter on stream0.
// ---------------------------------------------------------------------------
struct PipeCtx {
    cudaStream_t s1;
    cudaEvent_t  evFork, evJoin;
};
static PipeCtx& pipe_ctx() {
    static PipeCtx c = [] {
        PipeCtx t;
        cudaStreamCreateWithFlags(&t.s1, cudaStreamNonBlocking);
        cudaEventCreateWithFlags(&t.evFork, cudaEventDisableTiming);
        cudaEventCreateWithFlags(&t.evJoin, cudaEventDisableTiming);
        return t;
    }();
    return c;
}

extern "C" void kernel_launch(void* const* d_in, const int* in_sizes, int n_in,
                              void* d_out, int out_size) {
    const float* x     = (const float*)d_in[0];
    const void*  ei    = d_in[1];
    const void*  et    = d_in[2];
    const float* wrel  = (const float*)d_in[3];
    const float* wself = (const float*)d_in[4];
    const float* bias  = (const float*)d_in[5];
    float*       out   = (float*)d_out;

    PipeCtx& c = pipe_ctx();

    // fork s1 off stream 0
    cudaEventRecord(c.evFork, 0);
    cudaStreamWaitEvent(c.s1, c.evFork, 0);

    // s1: edge prep chain
    zero_detect_kernel<<<(N_NODES * NREL + 255) / 256, 256, 0, c.s1>>>(ei);
    deg_kernel<<<(NEDGES + 255) / 256, 256, 0, c.s1>>>(ei, et);
    epack_kernel<<<(NEDGES + 255) / 256, 256, 0, c.s1>>>(ei, et);
    cudaEventRecord(c.evJoin, c.s1);

    // stream 0: GEMM chain (single xw launch, full grid)
    wprep_kernel<<<(NMAT * 8 * 1024 + 255) / 256, 256>>>(wrel, wself);
    xh_kernel<<<(MFRAG_PAD * 8 * 32 + 255) / 256, 256>>>(x);
    xw_kernel<<<dim3(NCHUNKM, NMAT), 256>>>(bias, out);

    // join, then scatter
    cudaStreamWaitEvent(0, c.evJoin, 0);
    scatter_kernel<<<((size_t)NEDGES * 16 + 255) / 256, 256>>>(out);
}